// round 2
// baseline (speedup 1.0000x reference)
#include <cuda_runtime.h>
#include <math.h>

#define BB 32
#define TT 512
#define HH 1024
#define G4 4096      // 4*H
#define KD 1024      // K dim (input_size == hidden_size)
#define NBLK 128     // persistent grid (<= 148 SMs, all co-resident)

// ---------------- scratch (device globals: allocation-free) ----------------
__device__ float g_xg[(size_t)BB * TT * G4];    // [B,T,4H] gate preactivations (input part)
__device__ float g_h0[(size_t)BB * TT * HH];    // layer-0 h sequence [B,T,H]
__device__ float g_h1buf[2 * BB * HH];          // layer-1 h ping-pong
__device__ unsigned g_barA = 0;                 // barrier counter, layer 0
__device__ unsigned g_barB = 0;                 // barrier counter, layer 1

// ---------------- big projection GEMM: out[m,n] = sum_k A[m,k]*W[n,k] + b1[n] + b2[n]
// M = B*T = 16384, N = 4096, K = 1024. 64x64 tile, BK=16, 256 threads, 4x4 micro.
__global__ __launch_bounds__(256) void xg_gemm(const float* __restrict__ A,
                                               const float* __restrict__ W,
                                               const float* __restrict__ b1,
                                               const float* __restrict__ b2,
                                               float* __restrict__ out) {
    __shared__ float As[16][68];
    __shared__ float Bs[16][68];
    const int bm = blockIdx.y * 64;
    const int bn = blockIdx.x * 64;
    const int t  = threadIdx.x;
    const int lr = t >> 2;           // 0..63 tile row
    const int lk = (t & 3) * 4;      // 0,4,8,12
    const int tx = t & 15, ty = t >> 4;

    float acc[4][4];
#pragma unroll
    for (int i = 0; i < 4; i++)
#pragma unroll
        for (int j = 0; j < 4; j++) acc[i][j] = 0.f;

    const float* Arow = A + (size_t)(bm + lr) * KD + lk;
    const float* Wrow = W + (size_t)(bn + lr) * KD + lk;

    for (int k0 = 0; k0 < KD; k0 += 16) {
        float4 av = *(const float4*)(Arow + k0);
        float4 wv = *(const float4*)(Wrow + k0);
        As[lk + 0][lr] = av.x; As[lk + 1][lr] = av.y;
        As[lk + 2][lr] = av.z; As[lk + 3][lr] = av.w;
        Bs[lk + 0][lr] = wv.x; Bs[lk + 1][lr] = wv.y;
        Bs[lk + 2][lr] = wv.z; Bs[lk + 3][lr] = wv.w;
        __syncthreads();
#pragma unroll
        for (int k = 0; k < 16; k++) {
            float4 a = *(const float4*)&As[k][ty * 4];
            float4 b = *(const float4*)&Bs[k][tx * 4];
            acc[0][0] += a.x * b.x; acc[0][1] += a.x * b.y; acc[0][2] += a.x * b.z; acc[0][3] += a.x * b.w;
            acc[1][0] += a.y * b.x; acc[1][1] += a.y * b.y; acc[1][2] += a.y * b.z; acc[1][3] += a.y * b.w;
            acc[2][0] += a.z * b.x; acc[2][1] += a.z * b.y; acc[2][2] += a.z * b.z; acc[2][3] += a.z * b.w;
            acc[3][0] += a.w * b.x; acc[3][1] += a.w * b.y; acc[3][2] += a.w * b.z; acc[3][3] += a.w * b.w;
        }
        __syncthreads();
    }

#pragma unroll
    for (int j = 0; j < 4; j++) {
        int n = bn + tx * 4 + j;
        float bias = b1[n] + b2[n];
#pragma unroll
        for (int i = 0; i < 4; i++) {
            int m = bm + ty * 4 + i;
            out[(size_t)m * G4 + n] = acc[i][j] + bias;
        }
    }
}

// ---------------- grid-wide barrier (all NBLK blocks co-resident) ----------
__device__ __forceinline__ void grid_sync(unsigned* bar, unsigned target) {
    __syncthreads();
    if (threadIdx.x == 0) {
        __threadfence();                       // release: h writes visible
        atomicAdd(bar, 1u);
        while (*((volatile unsigned*)bar) < target) { __nanosleep(64); }
        __threadfence();                       // acquire-ish before consuming
    }
    __syncthreads();
}

__device__ __forceinline__ float sigf(float x) { return 1.f / (1.f + __expf(-x)); }

// ---------------- persistent LSTM sequence kernel ----------------
// Each block owns j-tile of 8 hidden units (all 4 gates = 32 Whh rows), all 32
// batches. Loops over all T timesteps with a grid barrier between steps.
// Cell state c lives in a register per thread (thread->(b,j) mapping is fixed).
template <int LAYER>
__global__ __launch_bounds__(256) void lstm_seq(
    const float* __restrict__ Whh,     // [4H, H]
    const float* __restrict__ xg,      // [B,T,4H]
    float* __restrict__ h0seq,         // [B,T,H] layer0 output / layer1 residual input
    float* __restrict__ h1ping,        // [2*B*H]
    float* __restrict__ out)           // [B,T,H] (layer 1 only)
{
    __shared__ float Hs[32][36];
    __shared__ float Ws[32][36];
    __shared__ float Gs[32][33];

    const int t  = threadIdx.x;
    const int j0 = blockIdx.x * 8;
    const int tx = t & 31;          // col (gate*8 + j-local)
    const int ty = t >> 5;          // 0..7  (batch group of 4)
    const int lr = t >> 3;          // 0..31 load row
    const int lk = (t & 7) * 4;     // k quad
    const int wrow = ((lr >> 3) << 10) + j0 + (lr & 7);

    // reset the OTHER layer's barrier counter for the next launch (stream-
    // ordered; no concurrent user of that counter exists right now)
    if (t == 0) {
        if (LAYER == 0) g_barB = 0; else g_barA = 0;
    }
    unsigned* bar = (LAYER == 0) ? &g_barA : &g_barB;

    // pointwise identity for this thread (fixed across steps)
    const int b  = t >> 3;
    const int jl = t & 7;
    const int j  = j0 + jl;
    float c_reg = 0.f;

    const float* wp = Whh + (size_t)wrow * KD + lk;

    for (int step = 0; step < TT; step++) {
        if (step > 0) grid_sync(bar, (unsigned)(step * NBLK));

        float acc0 = 0.f, acc1 = 0.f, acc2 = 0.f, acc3 = 0.f;
        if (step > 0) {
            const float* hp = (LAYER == 0)
                ? h0seq + (size_t)lr * (TT * HH) + (size_t)(step - 1) * HH + lk
                : h1ping + (size_t)((step - 1) & 1) * (BB * HH) + (size_t)lr * HH + lk;
            for (int k0 = 0; k0 < KD; k0 += 32) {
                float4 hv = *(const float4*)(hp + k0);
                float4 wv = *(const float4*)(wp + k0);
                Hs[lk + 0][lr] = hv.x; Hs[lk + 1][lr] = hv.y;
                Hs[lk + 2][lr] = hv.z; Hs[lk + 3][lr] = hv.w;
                Ws[lk + 0][lr] = wv.x; Ws[lk + 1][lr] = wv.y;
                Ws[lk + 2][lr] = wv.z; Ws[lk + 3][lr] = wv.w;
                __syncthreads();
#pragma unroll
                for (int k = 0; k < 32; k++) {
                    float4 a = *(const float4*)&Hs[k][ty * 4];
                    float w  = Ws[k][tx];
                    acc0 += a.x * w; acc1 += a.y * w; acc2 += a.z * w; acc3 += a.w * w;
                }
                __syncthreads();
            }
        }

        Gs[tx][ty * 4 + 0] = acc0;
        Gs[tx][ty * 4 + 1] = acc1;
        Gs[tx][ty * 4 + 2] = acc2;
        Gs[tx][ty * 4 + 3] = acc3;
        __syncthreads();

        const size_t xb = (size_t)b * (TT * G4) + (size_t)step * G4;
        float gi = Gs[jl     ][b] + xg[xb + 0 * HH + j];
        float gf = Gs[8  + jl][b] + xg[xb + 1 * HH + j];
        float gg = Gs[16 + jl][b] + xg[xb + 2 * HH + j];
        float go = Gs[24 + jl][b] + xg[xb + 3 * HH + j];

        float iv = sigf(gi);
        float fv = sigf(gf);
        float gv = tanhf(gg);
        float ov = sigf(go);

        c_reg = fv * c_reg + iv * gv;
        float hv = ov * tanhf(c_reg);

        if (LAYER == 0) {
            h0seq[(size_t)b * (TT * HH) + (size_t)step * HH + j] = hv;
        } else {
            h1ping[(size_t)(step & 1) * (BB * HH) + (size_t)b * HH + j] = hv;
            size_t oi = (size_t)b * (TT * HH) + (size_t)step * HH + j;
            out[oi] = h0seq[oi] + hv;
        }
        // end-of-step sync happens at top of next iteration (no barrier
        // needed after the final step)
    }
}

// ---------------- launch ----------------
extern "C" void kernel_launch(void* const* d_in, const int* in_sizes, int n_in,
                              void* d_out, int out_size) {
    const float* x    = (const float*)d_in[0];
    const float* Wih0 = (const float*)d_in[1];
    const float* Whh0 = (const float*)d_in[2];
    const float* bih0 = (const float*)d_in[3];
    const float* bhh0 = (const float*)d_in[4];
    const float* Wih1 = (const float*)d_in[5];
    const float* Whh1 = (const float*)d_in[6];
    const float* bih1 = (const float*)d_in[7];
    const float* bhh1 = (const float*)d_in[8];
    float* outp = (float*)d_out;

    float *xgP, *h0P, *h1P;
    cudaGetSymbolAddress((void**)&xgP, g_xg);
    cudaGetSymbolAddress((void**)&h0P, g_h0);
    cudaGetSymbolAddress((void**)&h1P, g_h1buf);

    dim3 ggrid(G4 / 64, (BB * TT) / 64);

    // layer 0
    xg_gemm<<<ggrid, 256>>>(x, Wih0, bih0, bhh0, xgP);
    lstm_seq<0><<<NBLK, 256>>>(Whh0, xgP, h0P, h1P, outp);

    // layer 1 (residual into d_out)
    xg_gemm<<<ggrid, 256>>>(h0P, Wih1, bih1, bhh1, xgP);
    lstm_seq<1><<<NBLK, 256>>>(Whh1, xgP, h0P, h1P, outp);
}

// round 5
// speedup vs baseline: 3.9739x; 3.9739x over previous
#include <cuda_runtime.h>
#include <cuda_bf16.h>
#include <math.h>
#include <stdint.h>

#define BB 32
#define TT 512
#define HH 1024
#define G4 4096
#define KD 1024
#define NBLK 128

// ------------------------- device scratch (no allocs) -------------------------
__device__ float g_xg[(size_t)BB * TT * G4];                 // transposed: [t*32+b][4096]
__device__ __nv_bfloat16 g_xs_hi[(size_t)BB * TT * KD];      // x splits (GEMM0 A)
__device__ __nv_bfloat16 g_xs_lo[(size_t)BB * TT * KD];
__device__ __nv_bfloat16 g_h0_hi[(size_t)BB * TT * HH];      // layer0 h splits (GEMM1 A + residual)
__device__ __nv_bfloat16 g_h0_lo[(size_t)BB * TT * HH];
__device__ __nv_bfloat16 g_wi_hi[2][(size_t)G4 * KD];        // Wih splits
__device__ __nv_bfloat16 g_wi_lo[2][(size_t)G4 * KD];
__device__ __nv_bfloat16 g_wh_hi[2][(size_t)G4 * HH];        // Whh splits
__device__ __nv_bfloat16 g_wh_lo[2][(size_t)G4 * HH];
__device__ __align__(16) __nv_bfloat16 g_hfrag[2 * 65536];   // h in mma A-frag layout, ping-pong
__device__ unsigned g_barA = 0, g_barB = 0;

// ------------------------- helpers -------------------------
__device__ __forceinline__ uint32_t smem_u32(const void* p) {
    uint32_t a;
    asm("{ .reg .u64 t; cvta.to.shared.u64 t, %1; cvt.u32.u64 %0, t; }" : "=r"(a) : "l"(p));
    return a;
}
#define SWZ(x) ((x) ^ (((x) >> 3) & 0x70))

__device__ __forceinline__ void mma16816(float* c,
                                         uint32_t a0, uint32_t a1, uint32_t a2, uint32_t a3,
                                         uint32_t b0, uint32_t b1) {
    asm volatile("mma.sync.aligned.m16n8k16.row.col.f32.bf16.bf16.f32 "
                 "{%0,%1,%2,%3}, {%4,%5,%6,%7}, {%8,%9}, {%0,%1,%2,%3};"
                 : "+f"(c[0]), "+f"(c[1]), "+f"(c[2]), "+f"(c[3])
                 : "r"(a0), "r"(a1), "r"(a2), "r"(a3), "r"(b0), "r"(b1));
}
__device__ __forceinline__ void ldmx4(uint32_t* r, uint32_t addr) {
    asm volatile("ldmatrix.sync.aligned.m8n8.x4.shared.b16 {%0,%1,%2,%3}, [%4];"
                 : "=r"(r[0]), "=r"(r[1]), "=r"(r[2]), "=r"(r[3]) : "r"(addr));
}
__device__ __forceinline__ void ldmx2(uint32_t* r, uint32_t addr) {
    asm volatile("ldmatrix.sync.aligned.m8n8.x2.shared.b16 {%0,%1}, [%2];"
                 : "=r"(r[0]), "=r"(r[1]) : "r"(addr));
}

// ------------------------- fp32 -> bf16 hi/lo split -------------------------
__global__ void split_kernel(const float* __restrict__ src,
                             __nv_bfloat16* __restrict__ hi,
                             __nv_bfloat16* __restrict__ lo, int n) {
    int i = blockIdx.x * blockDim.x + threadIdx.x;
    if (i < n) {
        float x = src[i];
        __nv_bfloat16 h = __float2bfloat16(x);
        hi[i] = h;
        lo[i] = __float2bfloat16(x - __bfloat162float(h));
    }
}

// ------------------------- grid-wide barrier -------------------------
__device__ __forceinline__ void grid_sync(unsigned* bar, unsigned target) {
    __syncthreads();
    if (threadIdx.x == 0) {
        __threadfence();
        atomicAdd(bar, 1u);
        while (*((volatile unsigned*)bar) < target) { __nanosleep(64); }
        __threadfence();
    }
    __syncthreads();
}

__device__ __forceinline__ float sigf(float x) { return 1.f / (1.f + __expf(-x)); }

// ------------------------- projection GEMM (mma.sync, split-bf16 x3) -------------------------
// out[(t*32+b)][n] = sum_k A[m][k]*W[n][k] + b1[n] + b2[n]; m = b*512+t.
// Block tile 128x128, BK=64; 8 warps in 2(M)x4(N), warp tile 64x32.
#define PJ_AH 0
#define PJ_AL 16384
#define PJ_BH 32768
#define PJ_BL 49152
#define PJ_BIAS 65536
#define PJ_SMEM 66176

__global__ __launch_bounds__(256) void xg_gemm_mma(
    const __nv_bfloat16* __restrict__ Ahi, const __nv_bfloat16* __restrict__ Alo,
    const __nv_bfloat16* __restrict__ Whi, const __nv_bfloat16* __restrict__ Wlo,
    const float* __restrict__ b1, const float* __restrict__ b2,
    float* __restrict__ out)
{
    extern __shared__ __align__(1024) char smem[];
    const uint32_t sbase = smem_u32(smem);
    const int tid = threadIdx.x;
    const int wid = tid >> 5, lane = tid & 31;
    const int bm = blockIdx.y * 128;
    const int bn = blockIdx.x * 128;
    const int warpM = (wid & 1) * 64;
    const int warpN = (wid >> 1) * 32;

    if (tid < 128) ((float*)(smem + PJ_BIAS))[tid] = b1[bn + tid] + b2[bn + tid];

    float acc[4][4][4];
#pragma unroll
    for (int ma = 0; ma < 4; ma++)
#pragma unroll
        for (int na = 0; na < 4; na++)
#pragma unroll
            for (int i = 0; i < 4; i++) acc[ma][na][i] = 0.f;

    for (int c = 0; c < 16; c++) {
        // stage 4 tiles (Ah, Al, Bh, Bl), each 128 rows x 64 bf16, swizzled
#pragma unroll
        for (int i = 0; i < 16; i++) {
            int v = tid + (i << 8);
            int tile = v >> 10;
            int row = (v >> 3) & 127;
            int q = v & 7;
            const __nv_bfloat16* src = (tile == 0) ? Ahi : (tile == 1) ? Alo
                                       : (tile == 2) ? Whi : Wlo;
            int grow = ((tile < 2) ? bm : bn) + row;
            uint4 d = *(const uint4*)(src + (size_t)grow * KD + (c << 6) + (q << 3));
            uint32_t off = row * 128 + q * 16;
            *(uint4*)(smem + tile * 16384 + SWZ(off)) = d;
        }
        __syncthreads();

#pragma unroll
        for (int ks = 0; ks < 4; ks++) {
            uint32_t ah[4][4], al[4][4], bh[4][2], bl[4][2];
            const int arow = warpM + (lane & 15);
            const int akb = ks * 32 + (lane >> 4) * 16;
#pragma unroll
            for (int ma = 0; ma < 4; ma++) {
                uint32_t off = SWZ((uint32_t)((arow + ma * 16) * 128 + akb));
                ldmx4(ah[ma], sbase + PJ_AH + off);
                ldmx4(al[ma], sbase + PJ_AL + off);
            }
            const int brow = warpN + (lane & 7);
            const int bkb = ks * 32 + ((lane >> 3) & 1) * 16;
#pragma unroll
            for (int na = 0; na < 4; na++) {
                uint32_t off = SWZ((uint32_t)((brow + na * 8) * 128 + bkb));
                ldmx2(bh[na], sbase + PJ_BH + off);
                ldmx2(bl[na], sbase + PJ_BL + off);
            }
#pragma unroll
            for (int ma = 0; ma < 4; ma++)
#pragma unroll
                for (int na = 0; na < 4; na++) {
                    mma16816(acc[ma][na], ah[ma][0], ah[ma][1], ah[ma][2], ah[ma][3],
                             bh[na][0], bh[na][1]);
                    mma16816(acc[ma][na], ah[ma][0], ah[ma][1], ah[ma][2], ah[ma][3],
                             bl[na][0], bl[na][1]);
                    mma16816(acc[ma][na], al[ma][0], al[ma][1], al[ma][2], al[ma][3],
                             bh[na][0], bh[na][1]);
                }
        }
        __syncthreads();
    }

    // epilogue: write to transposed xg layout with bias
    const float* bsum = (const float*)(smem + PJ_BIAS);
#pragma unroll
    for (int ma = 0; ma < 4; ma++)
#pragma unroll
        for (int na = 0; na < 4; na++) {
            int nl = warpN + na * 8 + (lane & 3) * 2;
            int n = bn + nl;
            float bi0 = bsum[nl], bi1 = bsum[nl + 1];
#pragma unroll
            for (int half = 0; half < 2; half++) {
                int m = bm + warpM + ma * 16 + (lane >> 2) + half * 8;
                int orow = ((m & 511) << 5) + (m >> 9);
                float2 o = make_float2(acc[ma][na][half * 2] + bi0,
                                       acc[ma][na][half * 2 + 1] + bi1);
                *(float2*)(out + (size_t)orow * G4 + n) = o;
            }
        }
}

// ------------------------- persistent LSTM recurrence (mma.sync) -------------------------
// Block: j-tile of 8 hidden units (32 gate-cols), all 32 batches (M padded to 32 via 2 atoms).
// Warp w owns K-slice [w*128, w*128+128). Whh fragments (hi+lo) resident in REGISTERS.
// h stored in mma A-fragment layout (g_hfrag ping-pong) -> uint4 loads, no ldmatrix.
template <int LAYER>
__global__ __launch_bounds__(256, 1) void lstm_seq_mma(
    const __nv_bfloat16* __restrict__ WhhHi, const __nv_bfloat16* __restrict__ WhhLo,
    const float* __restrict__ xg,
    __nv_bfloat16* __restrict__ h0hi, __nv_bfloat16* __restrict__ h0lo,
    __nv_bfloat16* __restrict__ hfrag,
    float* __restrict__ out)
{
    __shared__ float Rs[8][32][34];
    __shared__ float xgs[32][32];

    const int tid = threadIdx.x;
    const int wid = tid >> 5, lane = tid & 31;
    const int j0 = blockIdx.x * 8;

    if (tid == 0) { if (LAYER == 0) g_barB = 0; else g_barA = 0; }
    unsigned* bar = (LAYER == 0) ? &g_barA : &g_barB;

    // preload Whh fragments for this warp's K-slice (hi + lo) into registers
    uint32_t Bh[8][4][2], Bl[8][4][2];
    {
        const int kbase = wid * 128;
#pragma unroll
        for (int kl = 0; kl < 8; kl++)
#pragma unroll
            for (int na = 0; na < 4; na++) {
                int grow = na * HH + j0 + (lane >> 2);   // gate na, hidden j0+(lane>>2)
                int k = kbase + kl * 16 + (lane & 3) * 2;
                const __nv_bfloat16* ph = WhhHi + (size_t)grow * HH + k;
                const __nv_bfloat16* pl = WhhLo + (size_t)grow * HH + k;
                Bh[kl][na][0] = *(const uint32_t*)ph;
                Bh[kl][na][1] = *(const uint32_t*)(ph + 8);
                Bl[kl][na][0] = *(const uint32_t*)pl;
                Bl[kl][na][1] = *(const uint32_t*)(pl + 8);
            }
    }

    // pointwise identity: thread -> (batch pb, j-local jl)
    const int pb = tid >> 3;
    const int jl = tid & 7;
    const int j = j0 + jl;
    float c_reg = 0.f;

    // h-fragment write index for (pb, j): layout [ks][mAtom][split][lane][8]
    const int f_r = pb & 15;
    const size_t f_base = (((((size_t)(j >> 4) * 2 + (pb >> 4)) * 2) * 32
                            + (f_r & 7) * 4 + ((j & 7) >> 1)) * 8)
                          + (((j >> 3) & 1) * 2 + (f_r >= 8)) * 2 + (j & 1);

    for (int step = 0; step < TT; step++) {
        if (step > 0) grid_sync(bar, (unsigned)(step * NBLK));

        // stage xg tile [32 batches x 32 gate-cols]
        {
            int b = tid >> 3, r = tid & 7;
            int g = r >> 1, p = r & 1;
            float4 d = *(const float4*)(xg + (size_t)((step << 5) + b) * G4 + (g << 10) + j0 + (p << 2));
            *(float4*)&xgs[b][g * 8 + p * 4] = d;
        }

        if (step > 0) {
            const __nv_bfloat16* hf = hfrag + (size_t)((step - 1) & 1) * 65536;
            float acc[2][4][4];
#pragma unroll
            for (int m = 0; m < 2; m++)
#pragma unroll
                for (int na = 0; na < 4; na++)
#pragma unroll
                    for (int i = 0; i < 4; i++) acc[m][na][i] = 0.f;

#pragma unroll
            for (int kl = 0; kl < 8; kl++) {
                const int ks = wid * 8 + kl;
#pragma unroll
                for (int m = 0; m < 2; m++) {
                    uint4 ahv = *(const uint4*)(hf + (size_t)(((ks * 2 + m) * 2 + 0) * 32 + lane) * 8);
                    uint4 alv = *(const uint4*)(hf + (size_t)(((ks * 2 + m) * 2 + 1) * 32 + lane) * 8);
                    const uint32_t* ah = (const uint32_t*)&ahv;
                    const uint32_t* al = (const uint32_t*)&alv;
#pragma unroll
                    for (int na = 0; na < 4; na++) {
                        mma16816(acc[m][na], ah[0], ah[1], ah[2], ah[3],
                                 Bh[kl][na][0], Bh[kl][na][1]);
                        mma16816(acc[m][na], ah[0], ah[1], ah[2], ah[3],
                                 Bl[kl][na][0], Bl[kl][na][1]);
                        mma16816(acc[m][na], al[0], al[1], al[2], al[3],
                                 Bh[kl][na][0], Bh[kl][na][1]);
                    }
                }
            }
            // store K-partials for cross-warp reduction
#pragma unroll
            for (int m = 0; m < 2; m++)
#pragma unroll
                for (int na = 0; na < 4; na++) {
                    int b0 = m * 16 + (lane >> 2);
                    int cc = na * 8 + (lane & 3) * 2;
                    *(float2*)&Rs[wid][b0][cc] = make_float2(acc[m][na][0], acc[m][na][1]);
                    *(float2*)&Rs[wid][b0 + 8][cc] = make_float2(acc[m][na][2], acc[m][na][3]);
                }
        }
        __syncthreads();

        // reduce across warps + pointwise
        float g0 = 0.f, g1 = 0.f, g2 = 0.f, g3 = 0.f;
        if (step > 0) {
#pragma unroll
            for (int w = 0; w < 8; w++) {
                g0 += Rs[w][pb][jl];
                g1 += Rs[w][pb][8 + jl];
                g2 += Rs[w][pb][16 + jl];
                g3 += Rs[w][pb][24 + jl];
            }
        }
        float gi = sigf(g0 + xgs[pb][jl]);
        float gf = sigf(g1 + xgs[pb][8 + jl]);
        float gg = tanhf(g2 + xgs[pb][16 + jl]);
        float go = sigf(g3 + xgs[pb][24 + jl]);
        c_reg = gf * c_reg + gi * gg;
        float hv = go * tanhf(c_reg);
        __nv_bfloat16 hh = __float2bfloat16(hv);
        __nv_bfloat16 hl = __float2bfloat16(hv - __bfloat162float(hh));

        __nv_bfloat16* hfn = hfrag + (size_t)(step & 1) * 65536;
        hfn[f_base] = hh;
        hfn[f_base + 256] = hl;          // split stride = 32 lanes * 8

        if (LAYER == 0) {
            size_t o = ((size_t)pb * TT + step) * HH + j;
            h0hi[o] = hh;
            h0lo[o] = hl;
        } else {
            size_t ro = ((size_t)pb * TT + step) * HH + j;
            float res = __bfloat162float(h0hi[ro]) + __bfloat162float(h0lo[ro]);
            out[ro] = hv + res;
        }
    }
}

// ------------------------- launch -------------------------
extern "C" void kernel_launch(void* const* d_in, const int* in_sizes, int n_in,
                              void* d_out, int out_size) {
    const float* x    = (const float*)d_in[0];
    const float* Wih0 = (const float*)d_in[1];
    const float* Whh0 = (const float*)d_in[2];
    const float* bih0 = (const float*)d_in[3];
    const float* bhh0 = (const float*)d_in[4];
    const float* Wih1 = (const float*)d_in[5];
    const float* Whh1 = (const float*)d_in[6];
    const float* bih1 = (const float*)d_in[7];
    const float* bhh1 = (const float*)d_in[8];
    float* outp = (float*)d_out;

    float* xgP;
    __nv_bfloat16 *xsH, *xsL, *h0H, *h0L, *wiH, *wiL, *whH, *whL, *hfP;
    cudaGetSymbolAddress((void**)&xgP, g_xg);
    cudaGetSymbolAddress((void**)&xsH, g_xs_hi);
    cudaGetSymbolAddress((void**)&xsL, g_xs_lo);
    cudaGetSymbolAddress((void**)&h0H, g_h0_hi);
    cudaGetSymbolAddress((void**)&h0L, g_h0_lo);
    cudaGetSymbolAddress((void**)&wiH, g_wi_hi);
    cudaGetSymbolAddress((void**)&wiL, g_wi_lo);
    cudaGetSymbolAddress((void**)&whH, g_wh_hi);
    cudaGetSymbolAddress((void**)&whL, g_wh_lo);
    cudaGetSymbolAddress((void**)&hfP, g_hfrag);

    cudaFuncSetAttribute(xg_gemm_mma, cudaFuncAttributeMaxDynamicSharedMemorySize, PJ_SMEM);

    const size_t WN = (size_t)G4 * KD;   // 4194304
    const int NX = BB * TT * KD;         // 16777216

    split_kernel<<<(NX + 255) / 256, 256>>>(x, xsH, xsL, NX);
    split_kernel<<<((int)WN + 255) / 256, 256>>>(Wih0, wiH, wiL, (int)WN);
    split_kernel<<<((int)WN + 255) / 256, 256>>>(Whh0, whH, whL, (int)WN);
    split_kernel<<<((int)WN + 255) / 256, 256>>>(Wih1, wiH + WN, wiL + WN, (int)WN);
    split_kernel<<<((int)WN + 255) / 256, 256>>>(Whh1, whH + WN, whL + WN, (int)WN);

    dim3 ggrid(G4 / 128, (BB * TT) / 128);

    // layer 0
    xg_gemm_mma<<<ggrid, 256, PJ_SMEM>>>(xsH, xsL, wiH, wiL, bih0, bhh0, xgP);
    lstm_seq_mma<0><<<NBLK, 256>>>(whH, whL, xgP, h0H, h0L, hfP, outp);

    // layer 1 (residual into d_out)
    xg_gemm_mma<<<ggrid, 256, PJ_SMEM>>>(h0H, h0L, wiH + WN, wiL + WN, bih1, bhh1, xgP);
    lstm_seq_mma<1><<<NBLK, 256>>>(whH + WN, whL + WN, xgP, h0H, h0L, hfP, outp);
}

// round 6
// speedup vs baseline: 4.9091x; 1.2353x over previous
#include <cuda_runtime.h>
#include <cuda_bf16.h>
#include <math.h>
#include <stdint.h>

#define BB 32
#define TT 512
#define HH 1024
#define G4 4096
#define KD 1024
#define NBLK 128

// ------------------------- device scratch (no allocs) -------------------------
__device__ float g_xg[(size_t)BB * TT * G4];                 // transposed: [t*32+b][4096]
__device__ __nv_bfloat16 g_xs_hi[(size_t)BB * TT * KD];
__device__ __nv_bfloat16 g_xs_lo[(size_t)BB * TT * KD];
__device__ __nv_bfloat16 g_h0_hi[(size_t)BB * TT * HH];
__device__ __nv_bfloat16 g_h0_lo[(size_t)BB * TT * HH];
__device__ __nv_bfloat16 g_wi_hi[2][(size_t)G4 * KD];
__device__ __nv_bfloat16 g_wi_lo[2][(size_t)G4 * KD];
__device__ __nv_bfloat16 g_wh_hi[2][(size_t)G4 * HH];
__device__ __nv_bfloat16 g_wh_lo[2][(size_t)G4 * HH];
__device__ __align__(16) __nv_bfloat16 g_hfrag[2 * 65536];   // h in mma A-frag layout, ping-pong
__device__ unsigned g_barA = 0, g_barB = 0;

// ------------------------- helpers -------------------------
__device__ __forceinline__ uint32_t smem_u32(const void* p) {
    uint32_t a;
    asm("{ .reg .u64 t; cvta.to.shared.u64 t, %1; cvt.u32.u64 %0, t; }" : "=r"(a) : "l"(p));
    return a;
}
#define SWZ(x) ((x) ^ (((x) >> 3) & 0x70))

__device__ __forceinline__ void mma16816(float* c,
                                         uint32_t a0, uint32_t a1, uint32_t a2, uint32_t a3,
                                         uint32_t b0, uint32_t b1) {
    asm volatile("mma.sync.aligned.m16n8k16.row.col.f32.bf16.bf16.f32 "
                 "{%0,%1,%2,%3}, {%4,%5,%6,%7}, {%8,%9}, {%0,%1,%2,%3};"
                 : "+f"(c[0]), "+f"(c[1]), "+f"(c[2]), "+f"(c[3])
                 : "r"(a0), "r"(a1), "r"(a2), "r"(a3), "r"(b0), "r"(b1));
}
__device__ __forceinline__ void ldmx4(uint32_t* r, uint32_t addr) {
    asm volatile("ldmatrix.sync.aligned.m8n8.x4.shared.b16 {%0,%1,%2,%3}, [%4];"
                 : "=r"(r[0]), "=r"(r[1]), "=r"(r[2]), "=r"(r[3]) : "r"(addr));
}
__device__ __forceinline__ void ldmx2(uint32_t* r, uint32_t addr) {
    asm volatile("ldmatrix.sync.aligned.m8n8.x2.shared.b16 {%0,%1}, [%2];"
                 : "=r"(r[0]), "=r"(r[1]) : "r"(addr));
}
__device__ __forceinline__ void cpasync16(uint32_t s, const void* g) {
    asm volatile("cp.async.cg.shared.global [%0], [%1], 16;" :: "r"(s), "l"(g));
}
__device__ __forceinline__ void cp_commit() {
    asm volatile("cp.async.commit_group;" ::: "memory");
}
template <int N>
__device__ __forceinline__ void cp_wait() {
    asm volatile("cp.async.wait_group %0;" :: "n"(N) : "memory");
}

// ------------------------- fp32 -> bf16 hi/lo split -------------------------
__global__ void split_kernel(const float* __restrict__ src,
                             __nv_bfloat16* __restrict__ hi,
                             __nv_bfloat16* __restrict__ lo, int n) {
    int i = blockIdx.x * blockDim.x + threadIdx.x;
    if (i < n) {
        float x = src[i];
        __nv_bfloat16 h = __float2bfloat16(x);
        hi[i] = h;
        lo[i] = __float2bfloat16(x - __bfloat162float(h));
    }
}

__device__ __forceinline__ float sigf(float x) { return 1.f / (1.f + __expf(-x)); }

// ------------------------- projection GEMM (mma.sync, cp.async 2-stage) -------------------------
// out[(t*32+b)][n] = sum_k A[m][k]*W[n][k] + b1[n] + b2[n]; m = b*512+t.
// Block tile 128x128, BK=64; 8 warps in 2(M)x4(N), warp tile 64x32. Double-buffered smem.
#define PJ_STAGE 65536          // 4 tiles * 16KB per stage
#define PJ_BIAS  131072
#define PJ_SMEM  131648

__global__ __launch_bounds__(256) void xg_gemm_mma(
    const __nv_bfloat16* __restrict__ Ahi, const __nv_bfloat16* __restrict__ Alo,
    const __nv_bfloat16* __restrict__ Whi, const __nv_bfloat16* __restrict__ Wlo,
    const float* __restrict__ b1, const float* __restrict__ b2,
    float* __restrict__ out)
{
    extern __shared__ __align__(1024) char smem[];
    const uint32_t sbase = smem_u32(smem);
    const int tid = threadIdx.x;
    const int wid = tid >> 5, lane = tid & 31;
    const int bm = blockIdx.y * 128;
    const int bn = blockIdx.x * 128;
    const int warpM = (wid & 1) * 64;
    const int warpN = (wid >> 1) * 32;

    if (tid < 128) ((float*)(smem + PJ_BIAS))[tid] = b1[bn + tid] + b2[bn + tid];

    // per-thread staging identity (16 lines of 16B per chunk)
    float acc[4][4][4];
#pragma unroll
    for (int ma = 0; ma < 4; ma++)
#pragma unroll
        for (int na = 0; na < 4; na++)
#pragma unroll
            for (int i = 0; i < 4; i++) acc[ma][na][i] = 0.f;

    auto issue_chunk = [&](int c, int stage) {
#pragma unroll
        for (int i = 0; i < 16; i++) {
            int v = tid + (i << 8);
            int tile = v >> 10;
            int row = (v >> 3) & 127;
            int q = v & 7;
            const __nv_bfloat16* src = (tile == 0) ? Ahi : (tile == 1) ? Alo
                                       : (tile == 2) ? Whi : Wlo;
            int grow = ((tile < 2) ? bm : bn) + row;
            uint32_t off = row * 128 + q * 16;
            cpasync16(sbase + stage * PJ_STAGE + tile * 16384 + SWZ(off),
                      src + (size_t)grow * KD + (c << 6) + (q << 3));
        }
        cp_commit();
    };

    issue_chunk(0, 0);

    for (int c = 0; c < 16; c++) {
        const int st = c & 1;
        if (c < 15) {
            issue_chunk(c + 1, st ^ 1);
            cp_wait<1>();
        } else {
            cp_wait<0>();
        }
        __syncthreads();

        const uint32_t stb = sbase + st * PJ_STAGE;
#pragma unroll
        for (int ks = 0; ks < 4; ks++) {
            uint32_t ah[4][4], al[4][4], bh[4][2], bl[4][2];
            const int arow = warpM + (lane & 15);
            const int akb = ks * 32 + (lane >> 4) * 16;
#pragma unroll
            for (int ma = 0; ma < 4; ma++) {
                uint32_t off = SWZ((uint32_t)((arow + ma * 16) * 128 + akb));
                ldmx4(ah[ma], stb + off);
                ldmx4(al[ma], stb + 16384 + off);
            }
            const int brow = warpN + (lane & 7);
            const int bkb = ks * 32 + ((lane >> 3) & 1) * 16;
#pragma unroll
            for (int na = 0; na < 4; na++) {
                uint32_t off = SWZ((uint32_t)((brow + na * 8) * 128 + bkb));
                ldmx2(bh[na], stb + 32768 + off);
                ldmx2(bl[na], stb + 49152 + off);
            }
#pragma unroll
            for (int ma = 0; ma < 4; ma++)
#pragma unroll
                for (int na = 0; na < 4; na++) {
                    mma16816(acc[ma][na], ah[ma][0], ah[ma][1], ah[ma][2], ah[ma][3],
                             bh[na][0], bh[na][1]);
                    mma16816(acc[ma][na], ah[ma][0], ah[ma][1], ah[ma][2], ah[ma][3],
                             bl[na][0], bl[na][1]);
                    mma16816(acc[ma][na], al[ma][0], al[ma][1], al[ma][2], al[ma][3],
                             bh[na][0], bh[na][1]);
                }
        }
        __syncthreads();
    }

    // epilogue: write to transposed xg layout with bias
    const float* bsum = (const float*)(smem + PJ_BIAS);
#pragma unroll
    for (int ma = 0; ma < 4; ma++)
#pragma unroll
        for (int na = 0; na < 4; na++) {
            int nl = warpN + na * 8 + (lane & 3) * 2;
            int n = bn + nl;
            float bi0 = bsum[nl], bi1 = bsum[nl + 1];
#pragma unroll
            for (int half = 0; half < 2; half++) {
                int m = bm + warpM + ma * 16 + (lane >> 2) + half * 8;
                int orow = ((m & 511) << 5) + (m >> 9);
                float2 o = make_float2(acc[ma][na][half * 2] + bi0,
                                       acc[ma][na][half * 2 + 1] + bi1);
                *(float2*)(out + (size_t)orow * G4 + n) = o;
            }
        }
}

// ------------------------- persistent LSTM recurrence (mma.sync, pipelined) -------------------------
// Block: j-tile of 8 hidden units (32 gate-cols), 32 batches. Warp w owns K-slice
// [w*128, w*128+128); Whh fragments (hi+lo) in registers. h in mma A-frag layout
// (g_hfrag ping-pong). Distance-1 prefetch on the h-frag loads; split grid barrier:
// arrive right after h writes, tail work (out/residual, next xg prefetch) after arrive.
template <int LAYER>
__global__ __launch_bounds__(256, 1) void lstm_seq_mma(
    const __nv_bfloat16* __restrict__ WhhHi, const __nv_bfloat16* __restrict__ WhhLo,
    const float* __restrict__ xg,
    __nv_bfloat16* __restrict__ h0hi, __nv_bfloat16* __restrict__ h0lo,
    __nv_bfloat16* __restrict__ hfrag,
    float* __restrict__ out)
{
    __shared__ float Rs[8][32][34];
    __shared__ float xgs[32][32];

    const int tid = threadIdx.x;
    const int wid = tid >> 5, lane = tid & 31;
    const int j0 = blockIdx.x * 8;

    if (tid == 0) { if (LAYER == 0) g_barB = 0; else g_barA = 0; }
    unsigned* bar = (LAYER == 0) ? &g_barA : &g_barB;

    // preload Whh fragments (hi + lo) into registers
    uint32_t Bh[8][4][2], Bl[8][4][2];
    {
        const int kbase = wid * 128;
#pragma unroll
        for (int kl = 0; kl < 8; kl++)
#pragma unroll
            for (int na = 0; na < 4; na++) {
                int grow = na * HH + j0 + (lane >> 2);
                int k = kbase + kl * 16 + (lane & 3) * 2;
                const __nv_bfloat16* ph = WhhHi + (size_t)grow * HH + k;
                const __nv_bfloat16* pl = WhhLo + (size_t)grow * HH + k;
                Bh[kl][na][0] = *(const uint32_t*)ph;
                Bh[kl][na][1] = *(const uint32_t*)(ph + 8);
                Bl[kl][na][0] = *(const uint32_t*)pl;
                Bl[kl][na][1] = *(const uint32_t*)(pl + 8);
            }
    }

    // pointwise identity: thread -> (batch pb, j-local jl)
    const int pb = tid >> 3;
    const int jl = tid & 7;
    const int j = j0 + jl;
    float c_reg = 0.f;

    // h-fragment write index (same layout as R5)
    const int f_r = pb & 15;
    const size_t f_base = (((((size_t)(j >> 4) * 2 + (pb >> 4)) * 2) * 32
                            + (f_r & 7) * 4 + ((j & 7) >> 1)) * 8)
                          + (((j >> 3) & 1) * 2 + (f_r >= 8)) * 2 + (j & 1);

    // xg staging identity + step-0 prefetch
    const int xb = tid >> 3, xr = tid & 7;
    const int xgg = xr >> 1, xp = xr & 1;
    const size_t xoff = (size_t)xb * G4 + ((size_t)xgg << 10) + j0 + (xp << 2);
    float4 xreg = *(const float4*)(xg + xoff);

    for (int step = 0; step < TT; step++) {
        if (step > 0) {
            if (tid == 0) {
                const unsigned target = (unsigned)step * NBLK;
                while (*((volatile unsigned*)bar) < target) { }
                __threadfence();
            }
            __syncthreads();
        }

        // stage xg tile from prefetched register
        *(float4*)&xgs[xb][xgg * 8 + xp * 4] = xreg;

        if (step > 0) {
            const __nv_bfloat16* hb = hfrag + (size_t)((step - 1) & 1) * 65536
                                      + wid * 8192 + lane * 8;
            float acc[2][4][4];
#pragma unroll
            for (int m = 0; m < 2; m++)
#pragma unroll
                for (int na = 0; na < 4; na++)
#pragma unroll
                    for (int i = 0; i < 4; i++) acc[m][na][i] = 0.f;

            // distance-1 prefetch double buffer over kl
            uint4 cA[2][2];
#pragma unroll
            for (int m = 0; m < 2; m++)
#pragma unroll
                for (int sp = 0; sp < 2; sp++)
                    cA[m][sp] = *(const uint4*)(hb + m * 512 + sp * 256);

#pragma unroll
            for (int kl = 0; kl < 8; kl++) {
                uint4 nA[2][2];
                if (kl < 7) {
#pragma unroll
                    for (int m = 0; m < 2; m++)
#pragma unroll
                        for (int sp = 0; sp < 2; sp++)
                            nA[m][sp] = *(const uint4*)(hb + (kl + 1) * 1024 + m * 512 + sp * 256);
                }
#pragma unroll
                for (int m = 0; m < 2; m++) {
                    const uint32_t* ah = (const uint32_t*)&cA[m][0];
                    const uint32_t* al = (const uint32_t*)&cA[m][1];
#pragma unroll
                    for (int na = 0; na < 4; na++) {
                        mma16816(acc[m][na], ah[0], ah[1], ah[2], ah[3],
                                 Bh[kl][na][0], Bh[kl][na][1]);
                        mma16816(acc[m][na], ah[0], ah[1], ah[2], ah[3],
                                 Bl[kl][na][0], Bl[kl][na][1]);
                        mma16816(acc[m][na], al[0], al[1], al[2], al[3],
                                 Bh[kl][na][0], Bh[kl][na][1]);
                    }
                }
                if (kl < 7) {
#pragma unroll
                    for (int m = 0; m < 2; m++)
#pragma unroll
                        for (int sp = 0; sp < 2; sp++)
                            cA[m][sp] = nA[m][sp];
                }
            }

            // store K-partials for cross-warp reduction
#pragma unroll
            for (int m = 0; m < 2; m++)
#pragma unroll
                for (int na = 0; na < 4; na++) {
                    int b0 = m * 16 + (lane >> 2);
                    int cc = na * 8 + (lane & 3) * 2;
                    *(float2*)&Rs[wid][b0][cc] = make_float2(acc[m][na][0], acc[m][na][1]);
                    *(float2*)&Rs[wid][b0 + 8][cc] = make_float2(acc[m][na][2], acc[m][na][3]);
                }
        }
        __syncthreads();

        // reduce across warps + pointwise
        float g0 = 0.f, g1 = 0.f, g2 = 0.f, g3 = 0.f;
        if (step > 0) {
#pragma unroll
            for (int w = 0; w < 8; w++) {
                g0 += Rs[w][pb][jl];
                g1 += Rs[w][pb][8 + jl];
                g2 += Rs[w][pb][16 + jl];
                g3 += Rs[w][pb][24 + jl];
            }
        }
        float gi = sigf(g0 + xgs[pb][jl]);
        float gf = sigf(g1 + xgs[pb][8 + jl]);
        float gg = tanhf(g2 + xgs[pb][16 + jl]);
        float go = sigf(g3 + xgs[pb][24 + jl]);
        c_reg = gf * c_reg + gi * gg;
        float hv = go * tanhf(c_reg);
        __nv_bfloat16 hh = __float2bfloat16(hv);
        __nv_bfloat16 hl = __float2bfloat16(hv - __bfloat162float(hh));

        __nv_bfloat16* hfn = hfrag + (size_t)(step & 1) * 65536;
        hfn[f_base] = hh;
        hfn[f_base + 256] = hl;

        // arrive as soon as h-frag writes are globally visible
        __syncthreads();
        if (tid == 0) { __threadfence(); atomicAdd(bar, 1u); }

        // tail work, hidden under other blocks' arrival
        if (LAYER == 0) {
            size_t o = ((size_t)pb * TT + step) * HH + j;
            h0hi[o] = hh;
            h0lo[o] = hl;
        } else {
            size_t ro = ((size_t)pb * TT + step) * HH + j;
            float res = __bfloat162float(h0hi[ro]) + __bfloat162float(h0lo[ro]);
            out[ro] = hv + res;
        }
        if (step + 1 < TT)
            xreg = *(const float4*)(xg + (size_t)(step + 1) * (32 * G4) + xoff);
    }
}

// ------------------------- launch -------------------------
extern "C" void kernel_launch(void* const* d_in, const int* in_sizes, int n_in,
                              void* d_out, int out_size) {
    const float* x    = (const float*)d_in[0];
    const float* Wih0 = (const float*)d_in[1];
    const float* Whh0 = (const float*)d_in[2];
    const float* bih0 = (const float*)d_in[3];
    const float* bhh0 = (const float*)d_in[4];
    const float* Wih1 = (const float*)d_in[5];
    const float* Whh1 = (const float*)d_in[6];
    const float* bih1 = (const float*)d_in[7];
    const float* bhh1 = (const float*)d_in[8];
    float* outp = (float*)d_out;

    float* xgP;
    __nv_bfloat16 *xsH, *xsL, *h0H, *h0L, *wiH, *wiL, *whH, *whL, *hfP;
    cudaGetSymbolAddress((void**)&xgP, g_xg);
    cudaGetSymbolAddress((void**)&xsH, g_xs_hi);
    cudaGetSymbolAddress((void**)&xsL, g_xs_lo);
    cudaGetSymbolAddress((void**)&h0H, g_h0_hi);
    cudaGetSymbolAddress((void**)&h0L, g_h0_lo);
    cudaGetSymbolAddress((void**)&wiH, g_wi_hi);
    cudaGetSymbolAddress((void**)&wiL, g_wi_lo);
    cudaGetSymbolAddress((void**)&whH, g_wh_hi);
    cudaGetSymbolAddress((void**)&whL, g_wh_lo);
    cudaGetSymbolAddress((void**)&hfP, g_hfrag);

    cudaFuncSetAttribute(xg_gemm_mma, cudaFuncAttributeMaxDynamicSharedMemorySize, PJ_SMEM);

    const size_t WN = (size_t)G4 * KD;   // 4194304
    const int NX = BB * TT * KD;         // 16777216

    split_kernel<<<(NX + 255) / 256, 256>>>(x, xsH, xsL, NX);
    split_kernel<<<((int)WN + 255) / 256, 256>>>(Wih0, wiH, wiL, (int)WN);
    split_kernel<<<((int)WN + 255) / 256, 256>>>(Whh0, whH, whL, (int)WN);
    split_kernel<<<((int)WN + 255) / 256, 256>>>(Wih1, wiH + WN, wiL + WN, (int)WN);
    split_kernel<<<((int)WN + 255) / 256, 256>>>(Whh1, whH + WN, whL + WN, (int)WN);

    dim3 ggrid(G4 / 128, (BB * TT) / 128);

    // layer 0
    xg_gemm_mma<<<ggrid, 256, PJ_SMEM>>>(xsH, xsL, wiH, wiL, bih0, bhh0, xgP);
    lstm_seq_mma<0><<<NBLK, 256>>>(whH, whL, xgP, h0H, h0L, hfP, outp);

    // layer 1 (residual into d_out)
    xg_gemm_mma<<<ggrid, 256, PJ_SMEM>>>(h0H, h0L, wiH + WN, wiL + WN, bih1, bhh1, xgP);
    lstm_seq_mma<1><<<NBLK, 256>>>(whH + WN, whL + WN, xgP, h0H, h0L, hfP, outp);
}